// round 15
// baseline (speedup 1.0000x reference)
#include <cuda_runtime.h>
#include <cuda_fp16.h>
#include <cstdint>
#include <cstddef>

#define B_  4
#define S_  2048
#define D_  1024

typedef __half h16;

// ---------------- scratch (static __device__: allocation-free) ----------------
__device__ h16 g_xh[(size_t)B_*S_*D_];           // x rounded to fp16
__device__ h16 g_Wqth[D_*D_], g_Wqtl[D_*D_];     // Wq^T [d,e] split
__device__ h16 g_Wkth[D_*D_], g_Wktl[D_*D_];     // Wk^T [d,e] split
__device__ h16 g_Wvh[D_*D_];                     // Wv rounded
__device__ float g_Mf[4 * (size_t)D_ * D_];      // split-K partials for Mt
__device__ h16 g_Mth[D_*D_];                     // Mt rounded
__device__ h16 g_Yh[(size_t)B_*S_*D_];           // Y = x @ Mt^T (rounded)
__device__ h16 g_Vth[(size_t)B_*S_*D_];          // [b][d][s] (rounded)
__device__ h16 g_E[(size_t)B_*S_*S_];            // exp(scores) fp16, unnormalized
__device__ float g_Rpart[8 * (size_t)B_*S_];     // per-(n-tile) row-sum partials
__device__ float g_Rinv[(size_t)B_*S_];          // 1 / rowsum(E)

// ---------------- sm_80-era primitives (valid on plain sm_100) ----------------
__device__ __forceinline__ uint32_t smem_u32(const void* p) {
    uint32_t a;
    asm("{ .reg .u64 t; cvta.to.shared.u64 t, %1; cvt.u32.u64 %0, t; }" : "=r"(a) : "l"(p));
    return a;
}
__device__ __forceinline__ void cp16(uint32_t dst, const void* src) {
    asm volatile("cp.async.cg.shared.global [%0], [%1], 16;" :: "r"(dst), "l"(src));
}
__device__ __forceinline__ void cp_commit() {
    asm volatile("cp.async.commit_group;" ::: "memory");
}
template <int N>
__device__ __forceinline__ void cp_wait() {
    asm volatile("cp.async.wait_group %0;" :: "n"(N) : "memory");
}
__device__ __forceinline__ void ldsm_x4(uint32_t& r0, uint32_t& r1, uint32_t& r2, uint32_t& r3,
                                        uint32_t addr) {
    asm volatile("ldmatrix.sync.aligned.m8n8.x4.shared.b16 {%0,%1,%2,%3}, [%4];"
                 : "=r"(r0), "=r"(r1), "=r"(r2), "=r"(r3) : "r"(addr));
}
__device__ __forceinline__ void mma16816(float* c, const uint32_t* a, uint32_t b0, uint32_t b1) {
    asm volatile(
        "mma.sync.aligned.m16n8k16.row.col.f32.f16.f16.f32 "
        "{%0,%1,%2,%3}, {%4,%5,%6,%7}, {%8,%9}, {%0,%1,%2,%3};"
        : "+f"(c[0]), "+f"(c[1]), "+f"(c[2]), "+f"(c[3])
        : "r"(a[0]), "r"(a[1]), "r"(a[2]), "r"(a[3]), "r"(b0), "r"(b1));
}

#define ROWB      80
#define TILEB     (128 * ROWB)          // 10240 B (128-row operand tile)
#define TILEB_B   (256 * ROWB)          // 20480 B (256-row B tile, wide path)
#define SM2       (3 * 3 * TILEB)       //  92160: Mt path (3 stages x 3 tiles)
#define STBW      (TILEB + TILEB_B)     //  30720 per wide stage
#define SMW       (4 * STBW)            // 122880: wide path (4 stages)

// ---------------------------------------------------------------------------
// 2-term 128x128 body (Mt only): acc += ah*bh + al*bh. 3 stages, 2 syncs/chunk.
// ---------------------------------------------------------------------------
__device__ __forceinline__ void
gemm_body2(const h16* __restrict__ Ah, const h16* __restrict__ Al,
           const h16* __restrict__ Bh, float* __restrict__ Cf,
           int K, int ldA, int ldB, int ldC,
           int m0, int n0, char* smem)
{
    constexpr int STB = 3 * TILEB;
    const uint32_t sbase = smem_u32(smem);
    const int tid  = threadIdx.x;
    const int warp = tid >> 5;
    const int lane = tid & 31;
    const int wm = (warp >> 2) * 64;
    const int wn = (warp & 3) * 32;
    const int nch = K >> 5;

    float acc[4][4][4];
#pragma unroll
    for (int mi = 0; mi < 4; mi++)
#pragma unroll
        for (int ni = 0; ni < 4; ni++)
#pragma unroll
            for (int r = 0; r < 4; r++) acc[mi][ni][r] = 0.f;

    const int row0 = tid >> 2;
    const int seg  = tid & 3;

    auto issue = [&](int kc, int st) {
        const int kk = kc << 5;
        const uint32_t s0 = sbase + st * STB;
#pragma unroll
        for (int p = 0; p < 2; p++) {
            const int row = row0 + p * 64;
            const size_t goA = (size_t)(m0 + row) * ldA + kk;
            const size_t goB = (size_t)(n0 + row) * ldB + kk;
            const uint32_t so = row * ROWB + seg * 16;
            cp16(s0 + 0 * TILEB + so, (const char*)(Ah + goA) + seg * 16);
            cp16(s0 + 1 * TILEB + so, (const char*)(Al + goA) + seg * 16);
            cp16(s0 + 2 * TILEB + so, (const char*)(Bh + goB) + seg * 16);
        }
        cp_commit();
    };

    issue(0, 0);
    issue(1, 1);

    for (int kc = 0; kc < nch; kc++) {
        const int st = kc % 3;
        if (kc + 2 < nch) issue(kc + 2, (kc + 2) % 3);
        else              cp_commit();
        cp_wait<2>();
        __syncthreads();

        const uint32_t s0 = sbase + st * STB;
        const uint32_t lrow = (lane & 15) * ROWB + (lane >> 4) * 16;

#pragma unroll
        for (int ks = 0; ks < 2; ks++) {
            uint32_t ah[4][4], al[4][4], bh[2][4];
#pragma unroll
            for (int mi = 0; mi < 4; mi++) {
                const uint32_t ro = (wm + mi * 16) * ROWB + lrow + ks * 32;
                ldsm_x4(ah[mi][0], ah[mi][1], ah[mi][2], ah[mi][3], s0 + 0 * TILEB + ro);
                ldsm_x4(al[mi][0], al[mi][1], al[mi][2], al[mi][3], s0 + 1 * TILEB + ro);
            }
#pragma unroll
            for (int nb = 0; nb < 2; nb++) {
                const uint32_t ro = (wn + nb * 16) * ROWB + lrow + ks * 32;
                ldsm_x4(bh[nb][0], bh[nb][1], bh[nb][2], bh[nb][3], s0 + 2 * TILEB + ro);
            }
#pragma unroll
            for (int mi = 0; mi < 4; mi++)
#pragma unroll
                for (int ni = 0; ni < 4; ni++) {
                    const int g = ni >> 1, h = ni & 1;
                    mma16816(acc[mi][ni], ah[mi], bh[g][h], bh[g][h + 2]);
                    mma16816(acc[mi][ni], al[mi], bh[g][h], bh[g][h + 2]);
                }
        }
        __syncthreads();
    }

    const int rr = lane >> 2;
    const int cc = (lane & 3) * 2;
#pragma unroll
    for (int mi = 0; mi < 4; mi++)
#pragma unroll
        for (int ni = 0; ni < 4; ni++) {
            const int r = m0 + wm + mi * 16 + rr;
            const int c = n0 + wn + ni * 8 + cc;
            const float* a = acc[mi][ni];
#pragma unroll
            for (int h = 0; h < 2; h++) {
                float2 v; v.x = a[2*h]; v.y = a[2*h + 1];
                *(float2*)(Cf + (size_t)(r + h * 8) * ldC + c) = v;
            }
        }
}

__global__ void __launch_bounds__(256, 2)
mt_kernel(const h16* __restrict__ Wkth, const h16* __restrict__ Wktl,
          const h16* __restrict__ Wqth, float* __restrict__ Mf)
{
    extern __shared__ char smem[];
    gemm_body2(Wkth + blockIdx.z * 256, Wktl + blockIdx.z * 256,
               Wqth + blockIdx.z * 256, Mf + (size_t)blockIdx.z * D_ * D_,
               256, D_, D_, D_, blockIdx.y * 128, blockIdx.x * 128, smem);
}

// ---------------------------------------------------------------------------
// WIDE 1-term body: CTA tile 128x256, warp tile 64x64 (2m x 4n warps).
// 4 stages, prefetch distance 2, SINGLE sync per chunk (hazard proof: issue at
// iter kc writes stage (kc+2)&3, last read at iter kc-2; every warp reaching
// the issue passed sync(kc-1), which requires compute(kc-2) finished).
// EPI 2: Chi = fp16(acc)
// EPI 3: Chi = fp16(expf(alpha*acc)) + per-row partials -> Rp
// EPI 4: Cf  = acc * Rs[col]
// ---------------------------------------------------------------------------
template <int EPI>
__device__ __forceinline__ void
gemm_body_w(const h16* __restrict__ Ah, const h16* __restrict__ Bh,
            h16* __restrict__ Chi, float* __restrict__ Cf,
            const float* __restrict__ Rs, float* __restrict__ Rp,
            int K, int ldA, int ldB, int ldC, float alpha,
            int m0, int n0, char* smem)
{
    const uint32_t sbase = smem_u32(smem);
    const int tid  = threadIdx.x;
    const int warp = tid >> 5;
    const int lane = tid & 31;
    const int wm = (warp >> 2) * 64;    // 0 or 64
    const int wn = (warp & 3) * 64;     // 0..192
    const int nch = K >> 5;

    float acc[4][8][4];
#pragma unroll
    for (int mi = 0; mi < 4; mi++)
#pragma unroll
        for (int ni = 0; ni < 8; ni++)
#pragma unroll
            for (int r = 0; r < 4; r++) acc[mi][ni][r] = 0.f;

    const int row0 = tid >> 2;          // 0..63
    const int seg  = tid & 3;

    auto issue = [&](int kc, int st) {
        const int kk = kc << 5;
        const uint32_t s0 = sbase + st * STBW;
#pragma unroll
        for (int p = 0; p < 2; p++) {   // A: 128 rows
            const int row = row0 + p * 64;
            cp16(s0 + row * ROWB + seg * 16,
                 (const char*)(Ah + (size_t)(m0 + row) * ldA + kk) + seg * 16);
        }
#pragma unroll
        for (int p = 0; p < 4; p++) {   // B: 256 rows
            const int row = row0 + p * 64;
            cp16(s0 + TILEB + row * ROWB + seg * 16,
                 (const char*)(Bh + (size_t)(n0 + row) * ldB + kk) + seg * 16);
        }
        cp_commit();
    };

    issue(0, 0);
    issue(1, 1);

    for (int kc = 0; kc < nch; kc++) {
        const int st = kc & 3;
        if (kc + 2 < nch) issue(kc + 2, (kc + 2) & 3);
        else              cp_commit();
        cp_wait<2>();
        __syncthreads();

        const uint32_t s0 = sbase + st * STBW;
        const uint32_t lrow = (lane & 15) * ROWB + (lane >> 4) * 16;

#pragma unroll
        for (int ks = 0; ks < 2; ks++) {
            uint32_t ah[4][4], bh[4][4];
#pragma unroll
            for (int mi = 0; mi < 4; mi++)
                ldsm_x4(ah[mi][0], ah[mi][1], ah[mi][2], ah[mi][3],
                        s0 + (wm + mi * 16) * ROWB + lrow + ks * 32);
#pragma unroll
            for (int nb = 0; nb < 4; nb++)
                ldsm_x4(bh[nb][0], bh[nb][1], bh[nb][2], bh[nb][3],
                        s0 + TILEB + (wn + nb * 16) * ROWB + lrow + ks * 32);
#pragma unroll
            for (int mi = 0; mi < 4; mi++)
#pragma unroll
                for (int ni = 0; ni < 8; ni++) {
                    const int g = ni >> 1, h = ni & 1;
                    mma16816(acc[mi][ni], ah[mi], bh[g][h], bh[g][h + 2]);
                }
        }
    }

    // ---- epilogue
    const int rr = lane >> 2;
    const int cc = (lane & 3) * 2;
    float rp[4][2];
    if (EPI == 3) {
#pragma unroll
        for (int mi = 0; mi < 4; mi++) { rp[mi][0] = 0.f; rp[mi][1] = 0.f; }
    }
#pragma unroll
    for (int mi = 0; mi < 4; mi++) {
#pragma unroll
        for (int ni = 0; ni < 8; ni++) {
            const int r = m0 + wm + mi * 16 + rr;
            const int c = n0 + wn + ni * 8 + cc;
            const float* a = acc[mi][ni];
            float rs0 = 0.f, rs1 = 0.f;
            if (EPI == 4) { rs0 = Rs[c]; rs1 = Rs[c + 1]; }
#pragma unroll
            for (int h = 0; h < 2; h++) {
                const size_t o = (size_t)(r + h * 8) * ldC + c;
                if (EPI == 2) {
                    *(__half2*)(Chi + o) =
                        __halves2half2(__float2half_rn(a[2*h]), __float2half_rn(a[2*h + 1]));
                } else if (EPI == 3) {
                    float e0 = __expf(alpha * a[2*h]);
                    float e1 = __expf(alpha * a[2*h + 1]);
                    *(__half2*)(Chi + o) =
                        __halves2half2(__float2half_rn(e0), __float2half_rn(e1));
                    rp[mi][h] += e0 + e1;
                } else {    // EPI == 4
                    float2 v; v.x = a[2*h] * rs0; v.y = a[2*h + 1] * rs1;
                    *(float2*)(Cf + o) = v;
                }
            }
        }
    }
    if (EPI == 3) {
        // quad-reduce across 4 lanes sharing each row, combine across 4 n-warps
        float* sp = (float*)smem;       // stage 0 scratch; laggards read stage 3
        __syncthreads();
#pragma unroll
        for (int mi = 0; mi < 4; mi++)
#pragma unroll
            for (int h = 0; h < 2; h++) {
                float s = rp[mi][h];
                s += __shfl_xor_sync(0xFFFFFFFFu, s, 1);
                s += __shfl_xor_sync(0xFFFFFFFFu, s, 2);
                if ((lane & 3) == 0)
                    sp[(wm + mi * 16 + rr + h * 8) * 4 + (warp & 3)] = s;
            }
        __syncthreads();
        if (tid < 128)
            Rp[tid] = sp[tid * 4] + sp[tid * 4 + 1] + sp[tid * 4 + 2] + sp[tid * 4 + 3];
    }
}

// ---- wide wrapper: tiles on blockIdx.x (n, 256-wide) / y (m), batch on z ----
template <int EPI>
__global__ void __launch_bounds__(256, 1)
gemm_w(const h16* __restrict__ Ah, const h16* __restrict__ Bh,
       h16* __restrict__ Chi, float* __restrict__ Cf,
       const float* __restrict__ Rs, float* __restrict__ Rp,
       int K, int ldA, int ldB, int ldC, float alpha,
       size_t aStr, size_t bStr, size_t cStr)
{
    extern __shared__ char smem[];
    const size_t z = blockIdx.z;
    float* Rp_loc = (EPI == 3)
        ? Rp + (size_t)blockIdx.x * (B_ * S_) + z * S_ + blockIdx.y * 128 : nullptr;
    gemm_body_w<EPI>(Ah + z * aStr, Bh + z * bStr,
                     (EPI == 2 || EPI == 3) ? Chi + z * cStr : nullptr,
                     (EPI == 4) ? Cf + z * cStr : nullptr,
                     (EPI == 4) ? Rs + z * S_ : nullptr, Rp_loc,
                     K, ldA, ldB, ldC, alpha,
                     blockIdx.y * 128, blockIdx.x * 256, smem);
}

// ---- fused Y + Vt (wide): 512 CTAs ----
__global__ void __launch_bounds__(256, 1)
yvt_kernel(const h16* __restrict__ xh, const h16* __restrict__ Mth,
           const h16* __restrict__ Wvh, h16* __restrict__ Yh, h16* __restrict__ Vth)
{
    extern __shared__ char smem[];
    const int idx = blockIdx.x;
    if (idx < 256) {
        // Y[s,d'] = sum_d x[s,d] * Mt[d',d]   M=8192, N=1024 -> 64 x 4 tiles
        const int by = idx >> 2, bx = idx & 3;
        gemm_body_w<2>(xh, Mth, Yh, nullptr, nullptr, nullptr,
                       D_, D_, D_, D_, 1.f, by * 128, bx * 256, smem);
    } else {
        // Vt[b][d,s] = sum_e Wv[d,e] * x[b][s,e]   per batch 8 x 8 tiles
        const int j = idx - 256;
        const int bx = j & 7, by = (j >> 3) & 7, z = j >> 6;
        gemm_body_w<2>(Wvh, xh + (size_t)z * S_ * D_,
                       Vth + (size_t)z * D_ * S_, nullptr, nullptr, nullptr,
                       D_, D_, D_, S_, 1.f, by * 128, bx * 256, smem);
    }
}

// ---- reduce 4 split-K fp32 partials -> fp16 ----
__global__ void __launch_bounds__(256)
reduce4_h(const float* __restrict__ P, h16* __restrict__ outh, size_t n)
{
    size_t i = ((size_t)blockIdx.x * 256 + threadIdx.x) * 8;
    if (i >= n) return;
    h16 h[8];
#pragma unroll
    for (int q = 0; q < 2; q++) {
        size_t j = i + q * 4;
        float4 a = *(const float4*)(P + j);
        float4 b = *(const float4*)(P + n + j);
        float4 c = *(const float4*)(P + 2 * n + j);
        float4 d = *(const float4*)(P + 3 * n + j);
        h[q*4+0] = __float2half_rn(a.x + b.x + c.x + d.x);
        h[q*4+1] = __float2half_rn(a.y + b.y + c.y + d.y);
        h[q*4+2] = __float2half_rn(a.z + b.z + c.z + d.z);
        h[q*4+3] = __float2half_rn(a.w + b.w + c.w + d.w);
    }
    *(uint4*)(outh + i) = *(uint4*)h;
}

// ---- merged prep: fp32->fp16 rounds (x, Wv) + W^T hi/lo splits (Wq, Wk) ----
#define NCONV 4608
__global__ void __launch_bounds__(256)
prep_kernel(const float* __restrict__ x,  h16* __restrict__ xh,
            const float* __restrict__ Wv, h16* __restrict__ Wvh,
            const float* __restrict__ Wq, const float* __restrict__ Wk,
            h16* __restrict__ Qh, h16* __restrict__ Ql,
            h16* __restrict__ Kh, h16* __restrict__ Kl)
{
    const size_t nX = (size_t)B_ * S_ * D_;
    const size_t nW = (size_t)D_ * D_;
    const int tid = threadIdx.x;
    if (blockIdx.x < NCONV) {
        size_t i = ((size_t)blockIdx.x * 256 + tid) * 8;
        const float* in; h16* outp; size_t off;
        if (i < nX)           { in = x;  outp = xh;  off = i; }
        else if (i < nX + nW) { in = Wv; outp = Wvh; off = i - nX; }
        else return;
        float4 v0 = *(const float4*)(in + off);
        float4 v1 = *(const float4*)(in + off + 4);
        float f[8] = {v0.x, v0.y, v0.z, v0.w, v1.x, v1.y, v1.z, v1.w};
        h16 h[8];
#pragma unroll
        for (int j = 0; j < 8; j++) h[j] = __float2half_rn(f[j]);
        *(uint4*)(outp + off) = *(uint4*)h;
    } else {
        __shared__ float t[32][33];
        const int j  = blockIdx.x - NCONV;
        const int zz = j >> 10;
        const int by = (j >> 5) & 31;
        const int bx = j & 31;
        const float* W = zz ? Wk : Wq;
        h16* Th = zz ? Kh : Qh;
        h16* Tl = zz ? Kl : Ql;
        const int d0 = bx * 32, e0 = by * 32;
        const int tx = tid & 31, ty0 = tid >> 5;
#pragma unroll
        for (int q = 0; q < 4; q++) {
            int ty = ty0 + q * 8;
            t[ty][tx] = W[(size_t)(e0 + ty) * D_ + d0 + tx];
        }
        __syncthreads();
#pragma unroll
        for (int q = 0; q < 4; q++) {
            int ty = ty0 + q * 8;
            float v = t[tx][ty];
            h16 h = __float2half_rn(v);
            h16 l = __float2half_rn(v - __half2float(h));
            Th[(size_t)(d0 + ty) * D_ + e0 + tx] = h;
            Tl[(size_t)(d0 + ty) * D_ + e0 + tx] = l;
        }
    }
}

// ---- Rinv[i] = 1 / sum_{bx<8} Rpart[bx][i] ----
__global__ void __launch_bounds__(256)
rowsum8_inv(const float* __restrict__ Rp, float* __restrict__ Rinv)
{
    const int i = blockIdx.x * 256 + threadIdx.x;
    float s = 0.f;
#pragma unroll
    for (int j = 0; j < 8; j++) s += Rp[(size_t)j * (B_ * S_) + i];
    Rinv[i] = 1.f / s;
}

// ---------------------------------------------------------------------------
extern "C" void kernel_launch(void* const* d_in, const int* in_sizes, int n_in,
                              void* d_out, int out_size)
{
    const float* x  = (const float*)d_in[0];
    const float* Wq = (const float*)d_in[1];
    const float* Wk = (const float*)d_in[2];
    const float* Wv = (const float*)d_in[3];
    float* out = (float*)d_out;

    h16 *xh, *Wqth, *Wqtl, *Wkth, *Wktl, *Wvh, *Mth, *Yh, *Vth, *E;
    float *Mf, *Rpart, *Rinv;
    cudaGetSymbolAddress((void**)&xh,    g_xh);
    cudaGetSymbolAddress((void**)&Wqth,  g_Wqth); cudaGetSymbolAddress((void**)&Wqtl, g_Wqtl);
    cudaGetSymbolAddress((void**)&Wkth,  g_Wkth); cudaGetSymbolAddress((void**)&Wktl, g_Wktl);
    cudaGetSymbolAddress((void**)&Wvh,   g_Wvh);
    cudaGetSymbolAddress((void**)&Mf,    g_Mf);
    cudaGetSymbolAddress((void**)&Mth,   g_Mth);
    cudaGetSymbolAddress((void**)&Yh,    g_Yh);
    cudaGetSymbolAddress((void**)&Vth,   g_Vth);
    cudaGetSymbolAddress((void**)&E,     g_E);
    cudaGetSymbolAddress((void**)&Rpart, g_Rpart);
    cudaGetSymbolAddress((void**)&Rinv,  g_Rinv);

    cudaFuncSetAttribute(mt_kernel,  cudaFuncAttributeMaxDynamicSharedMemorySize, SM2);
    cudaFuncSetAttribute(gemm_w<3>,  cudaFuncAttributeMaxDynamicSharedMemorySize, SMW);
    cudaFuncSetAttribute(gemm_w<4>,  cudaFuncAttributeMaxDynamicSharedMemorySize, SMW);
    cudaFuncSetAttribute(yvt_kernel, cudaFuncAttributeMaxDynamicSharedMemorySize, SMW);

    const size_t nW = (size_t)D_ * D_;
    const size_t sQKV = (size_t)S_ * D_;
    const size_t sSS  = (size_t)S_ * S_;
    const size_t sDS  = (size_t)D_ * S_;

    // merged converts + transposed weight splits
    prep_kernel<<<NCONV + 2048, 256>>>(x, xh, Wv, Wvh, Wq, Wk,
                                       Wqth, Wqtl, Wkth, Wktl);

    // Mt = Wk^T-split @ Wq^T-rounded, split-K x4
    mt_kernel<<<dim3(8, 8, 4), 256, SM2>>>(Wkth, Wktl, Wqth, Mf);
    reduce4_h<<<512, 256>>>(Mf, Mth, nW);

    // fused: Y = x @ Mt^T  and  Vt[b] = Wv @ x[b]^T   (wide tiles)
    yvt_kernel<<<512, 256, SMW>>>(xh, Mth, Wvh, Yh, Vth);

    // E[b][q,k] = exp(scores/32) + row partials   (wide tiles)
    gemm_w<3><<<dim3(8, 16, B_), 256, SMW>>>(
        Yh, xh, E, nullptr, nullptr, Rpart,
        D_, D_, D_, S_, 0.03125f, sQKV, sQKV, sSS);

    // Rinv = 1 / rowsums
    rowsum8_inv<<<(B_ * S_) / 256, 256>>>(Rpart, Rinv);

    // out[b][d,s] = (Vt @ E^T) * Rinv   (wide tiles)
    gemm_w<4><<<dim3(8, 8, B_), 256, SMW>>>(
        Vth, E, nullptr, out, Rinv, nullptr,
        S_, S_, S_, S_, 1.f, sDS, sSS, sDS);
}

// round 16
// speedup vs baseline: 1.0889x; 1.0889x over previous
#include <cuda_runtime.h>
#include <cuda_fp16.h>
#include <cstdint>
#include <cstddef>

#define B_  4
#define S_  2048
#define D_  1024

typedef __half h16;

// ---------------- scratch (static __device__: allocation-free) ----------------
__device__ h16 g_xh[(size_t)B_*S_*D_];           // x rounded to fp16
__device__ h16 g_Wqth[D_*D_], g_Wqtl[D_*D_];     // Wq^T [d,e] split
__device__ h16 g_Wkth[D_*D_], g_Wktl[D_*D_];     // Wk^T [d,e] split
__device__ h16 g_Wvh[D_*D_];                     // Wv rounded
__device__ float g_Mf[4 * (size_t)D_ * D_];      // split-K partials for Mt
__device__ h16 g_Mth[D_*D_];                     // Mt rounded
__device__ h16 g_Yh[(size_t)B_*S_*D_];           // Y = x @ Mt^T (rounded)
__device__ h16 g_Vth[(size_t)B_*S_*D_];          // [b][d][s] (rounded)
__device__ h16 g_E[(size_t)B_*S_*S_];            // exp(scores) fp16, unnormalized
__device__ float g_Rpart[16 * (size_t)B_*S_];    // per-(n-tile) row-sum partials
__device__ float g_Rinv[(size_t)B_*S_];          // 1 / rowsum(E)

// ---------------- sm_80-era primitives (valid on plain sm_100) ----------------
__device__ __forceinline__ uint32_t smem_u32(const void* p) {
    uint32_t a;
    asm("{ .reg .u64 t; cvta.to.shared.u64 t, %1; cvt.u32.u64 %0, t; }" : "=r"(a) : "l"(p));
    return a;
}
__device__ __forceinline__ void cp16(uint32_t dst, const void* src) {
    asm volatile("cp.async.cg.shared.global [%0], [%1], 16;" :: "r"(dst), "l"(src));
}
__device__ __forceinline__ void cp_commit() {
    asm volatile("cp.async.commit_group;" ::: "memory");
}
template <int N>
__device__ __forceinline__ void cp_wait() {
    asm volatile("cp.async.wait_group %0;" :: "n"(N) : "memory");
}
__device__ __forceinline__ void ldsm_x4(uint32_t& r0, uint32_t& r1, uint32_t& r2, uint32_t& r3,
                                        uint32_t addr) {
    asm volatile("ldmatrix.sync.aligned.m8n8.x4.shared.b16 {%0,%1,%2,%3}, [%4];"
                 : "=r"(r0), "=r"(r1), "=r"(r2), "=r"(r3) : "r"(addr));
}
__device__ __forceinline__ void mma16816(float* c, const uint32_t* a, uint32_t b0, uint32_t b1) {
    asm volatile(
        "mma.sync.aligned.m16n8k16.row.col.f32.f16.f16.f32 "
        "{%0,%1,%2,%3}, {%4,%5,%6,%7}, {%8,%9}, {%0,%1,%2,%3};"
        : "+f"(c[0]), "+f"(c[1]), "+f"(c[2]), "+f"(c[3])
        : "r"(a[0]), "r"(a[1]), "r"(a[2]), "r"(a[3]), "r"(b0), "r"(b1));
}

// ---------------------------------------------------------------------------
// HMMA GEMM tile body: C[128,128] at (m0,n0) = f(A@B^T) over K.
// NTERM=2: ah*bh + al*bh (A split, B rounded; 3 stages, dist 2, 2 syncs/chunk)
// NTERM=1: plain fp16 ah*bh (5 stages, dist 3, SINGLE sync/chunk)
//   hazard proof (NST=5, DIST=3): issue at iter j writes stage (j+3)%5, last
//   read by compute(j-2) at iter j-2; a warp reaching issue(j) passed
//   sync(j-1), which all warps reach only after finishing compute(j-2).
// EPI 1: Cf = alpha*acc   EPI 2: Chi = fp16(acc)
// EPI 3: Chi = fp16(expf(alpha*acc)) + per-row partial sums -> Rp[row]
// EPI 4: Cf = acc * Rs[col]  (deferred softmax normalization)
// 256 threads, rows padded to 80 B (conflict-free ldmatrix).
// ---------------------------------------------------------------------------
#define ROWB      80
#define TILEB     (128 * ROWB)          // 10240 B per operand tile
#define SM2       (3 * 3 * TILEB)       //  92160 (NTERM=2: 3 stages x 3 tiles)
#define SM1       (5 * 2 * TILEB)       // 102400 (NTERM=1: 5 stages x 2 tiles)

template <int EPI, int NTERM>
__device__ __forceinline__ void
gemm_body(const h16* __restrict__ Ah, const h16* __restrict__ Al,
          const h16* __restrict__ Bh,
          h16* __restrict__ Chi, float* __restrict__ Cf,
          const float* __restrict__ Rs, float* __restrict__ Rp,
          int K, int ldA, int ldB, int ldC, float alpha,
          int m0, int n0, char* smem)
{
    constexpr int NT   = (NTERM == 2) ? 3 : 2;    // tiles per stage
    constexpr int NST  = (NTERM == 2) ? 3 : 5;    // pipeline stages
    constexpr int DIST = (NTERM == 2) ? 2 : 3;    // prefetch distance
    constexpr int STB  = NT * TILEB;

    const uint32_t sbase = smem_u32(smem);
    const int tid  = threadIdx.x;
    const int warp = tid >> 5;
    const int lane = tid & 31;

    const int wm = (warp >> 2) * 64;    // warp tile: 64 (m) x 32 (n)
    const int wn = (warp & 3) * 32;
    const int nch = K >> 5;             // K-chunks of 32 (>= 8 for all calls)

    float acc[4][4][4];
#pragma unroll
    for (int mi = 0; mi < 4; mi++)
#pragma unroll
        for (int ni = 0; ni < 4; ni++)
#pragma unroll
            for (int r = 0; r < 4; r++) acc[mi][ni][r] = 0.f;

    const int row0 = tid >> 2;          // 0..63 ; second row = +64
    const int seg  = tid & 3;           // 16B segment within 64B of row data

    auto issue = [&](int kc, int st) {
        const int kk = kc << 5;
        const uint32_t s0 = sbase + st * STB;
#pragma unroll
        for (int p = 0; p < 2; p++) {
            const int row = row0 + p * 64;
            const size_t goA = (size_t)(m0 + row) * ldA + kk;
            const size_t goB = (size_t)(n0 + row) * ldB + kk;
            const uint32_t so = row * ROWB + seg * 16;
            cp16(s0 + 0 * TILEB + so, (const char*)(Ah + goA) + seg * 16);
            if (NTERM == 2)
                cp16(s0 + 1 * TILEB + so, (const char*)(Al + goA) + seg * 16);
            cp16(s0 + (NT - 1) * TILEB + so, (const char*)(Bh + goB) + seg * 16);
        }
        cp_commit();
    };

    issue(0, 0);
    issue(1, 1);
    if (DIST == 3) issue(2, 2);

    for (int kc = 0; kc < nch; kc++) {
        const int st = kc % NST;
        if (kc + DIST < nch) issue(kc + DIST, (kc + DIST) % NST);
        else                 cp_commit();        // empty group keeps count uniform
        if (NTERM == 1) cp_wait<3>();            // group kc complete
        else            cp_wait<2>();
        __syncthreads();

        const uint32_t s0 = sbase + st * STB;
        const uint32_t lrow = (lane & 15) * ROWB + (lane >> 4) * 16;
        const uint32_t boff = (NT - 1) * TILEB;

#pragma unroll
        for (int ks = 0; ks < 2; ks++) {
            uint32_t ah[4][4], al[4][4], bh[2][4];
#pragma unroll
            for (int mi = 0; mi < 4; mi++) {
                const uint32_t ro = (wm + mi * 16) * ROWB + lrow + ks * 32;
                ldsm_x4(ah[mi][0], ah[mi][1], ah[mi][2], ah[mi][3], s0 + 0 * TILEB + ro);
                if (NTERM == 2)
                    ldsm_x4(al[mi][0], al[mi][1], al[mi][2], al[mi][3], s0 + 1 * TILEB + ro);
            }
#pragma unroll
            for (int nb = 0; nb < 2; nb++) {
                const uint32_t ro = (wn + nb * 16) * ROWB + lrow + ks * 32;
                ldsm_x4(bh[nb][0], bh[nb][1], bh[nb][2], bh[nb][3], s0 + boff + ro);
            }
#pragma unroll
            for (int mi = 0; mi < 4; mi++)
#pragma unroll
                for (int ni = 0; ni < 4; ni++) {
                    const int g = ni >> 1, h = ni & 1;
                    mma16816(acc[mi][ni], ah[mi], bh[g][h], bh[g][h + 2]);      // hi*hi
                    if (NTERM == 2)
                        mma16816(acc[mi][ni], al[mi], bh[g][h], bh[g][h + 2]);  // lo*hi
                }
        }
        if (NTERM == 2) __syncthreads();         // 3-stage path keeps trailing sync
    }

    // ---- epilogue: d0,d1 = row g, cols 2t,2t+1 ; d2,d3 = row g+8
    const int rr = lane >> 2;
    const int cc = (lane & 3) * 2;
    float rp[4][2];
    if (EPI == 3) {
#pragma unroll
        for (int mi = 0; mi < 4; mi++) { rp[mi][0] = 0.f; rp[mi][1] = 0.f; }
    }
#pragma unroll
    for (int mi = 0; mi < 4; mi++) {
#pragma unroll
        for (int ni = 0; ni < 4; ni++) {
            const int r = m0 + wm + mi * 16 + rr;
            const int c = n0 + wn + ni * 8 + cc;
            const float* a = acc[mi][ni];
            float rs0 = 0.f, rs1 = 0.f;
            if (EPI == 4) { rs0 = Rs[c]; rs1 = Rs[c + 1]; }
#pragma unroll
            for (int h = 0; h < 2; h++) {
                const size_t o = (size_t)(r + h * 8) * ldC + c;
                if (EPI == 2) {
                    *(__half2*)(Chi + o) =
                        __halves2half2(__float2half_rn(a[2*h]), __float2half_rn(a[2*h + 1]));
                } else if (EPI == 3) {
                    float e0 = __expf(alpha * a[2*h]);
                    float e1 = __expf(alpha * a[2*h + 1]);
                    *(__half2*)(Chi + o) =
                        __halves2half2(__float2half_rn(e0), __float2half_rn(e1));
                    rp[mi][h] += e0 + e1;
                } else if (EPI == 4) {
                    float2 v; v.x = a[2*h] * rs0; v.y = a[2*h + 1] * rs1;
                    *(float2*)(Cf + o) = v;
                } else {
                    float2 v; v.x = alpha * a[2*h]; v.y = alpha * a[2*h + 1];
                    *(float2*)(Cf + o) = v;
                }
            }
        }
    }
    if (EPI == 3) {
        // quad-reduce across the 4 lanes sharing each row, then 4-warp combine.
        // Scratch = stage 0 bytes [0,2KB); laggard warps on the final chunk read
        // stage (nch-1)%5 = 1 for K=1024 — disjoint region, no hazard.
        float* sp = (float*)smem;
#pragma unroll
        for (int mi = 0; mi < 4; mi++)
#pragma unroll
            for (int h = 0; h < 2; h++) {
                float s = rp[mi][h];
                s += __shfl_xor_sync(0xFFFFFFFFu, s, 1);
                s += __shfl_xor_sync(0xFFFFFFFFu, s, 2);
                if ((lane & 3) == 0)
                    sp[(wm + mi * 16 + rr + h * 8) * 4 + (warp & 3)] = s;
            }
        __syncthreads();
        if (tid < 128)
            Rp[tid] = sp[tid * 4] + sp[tid * 4 + 1] + sp[tid * 4 + 2] + sp[tid * 4 + 3];
    }
}

// ---- generic wrapper kernel (tiles on blockIdx.x/y, batch/split on z) ----
template <int EPI, int NTERM>
__global__ void __launch_bounds__(256, 2)
gemm_mma(const h16* __restrict__ Ah, const h16* __restrict__ Al,
         const h16* __restrict__ Bh,
         h16* __restrict__ Chi, float* __restrict__ Cf,
         const float* __restrict__ Rs, float* __restrict__ Rp,
         int K, int ldA, int ldB, int ldC, float alpha,
         size_t aStr, size_t bStr, size_t cStr)
{
    extern __shared__ char smem[];
    const size_t z = blockIdx.z;
    float* Rp_loc = (EPI == 3)
        ? Rp + (size_t)blockIdx.x * (B_ * S_) + z * S_ + blockIdx.y * 128 : nullptr;
    gemm_body<EPI, NTERM>(Ah + z * aStr, (NTERM == 2) ? Al + z * aStr : nullptr,
                          Bh + z * bStr,
                          (EPI == 2 || EPI == 3) ? Chi + z * cStr : nullptr,
                          (EPI == 1 || EPI == 4) ? Cf + z * cStr : nullptr,
                          (EPI == 4) ? Rs + z * S_ : nullptr, Rp_loc,
                          K, ldA, ldB, ldC, alpha,
                          blockIdx.y * 128, blockIdx.x * 128, smem);
}

// ---- fused Y + Vt kernel: 1024 linear CTAs, both 1-term fp16 K=1024 ----
__global__ void __launch_bounds__(256, 2)
yvt_kernel(const h16* __restrict__ xh, const h16* __restrict__ Mth,
           const h16* __restrict__ Wvh, h16* __restrict__ Yh, h16* __restrict__ Vth)
{
    extern __shared__ char smem[];
    const int idx = blockIdx.x;
    if (idx < 512) {
        // Y[s,d'] = sum_d x[s,d] * Mt[d',d]   M=8192, N=1024
        const int by = idx >> 3, bx = idx & 7;
        gemm_body<2, 1>(xh, nullptr, Mth, Yh, nullptr, nullptr, nullptr,
                        D_, D_, D_, D_, 1.f, by * 128, bx * 128, smem);
    } else {
        // Vt[b][d,s] = sum_e Wv[d,e] * x[b][s,e]   per batch: M=1024, N=2048
        const int j = idx - 512;
        const int bx = j & 15, by = (j >> 4) & 7, z = j >> 7;
        gemm_body<2, 1>(Wvh, nullptr, xh + (size_t)z * S_ * D_,
                        Vth + (size_t)z * D_ * S_, nullptr, nullptr, nullptr,
                        D_, D_, D_, S_, 1.f, by * 128, bx * 128, smem);
    }
}

// ---- reduce 4 split-K fp32 partials -> fp16 (8 elems/thread for MLP) ----
__global__ void __launch_bounds__(256)
reduce4_h(const float* __restrict__ P, h16* __restrict__ outh, size_t n)
{
    size_t i = ((size_t)blockIdx.x * 256 + threadIdx.x) * 8;
    if (i >= n) return;
    h16 h[8];
#pragma unroll
    for (int q = 0; q < 2; q++) {
        size_t j = i + q * 4;
        float4 a = *(const float4*)(P + j);
        float4 b = *(const float4*)(P + n + j);
        float4 c = *(const float4*)(P + 2 * n + j);
        float4 d = *(const float4*)(P + 3 * n + j);
        h[q*4+0] = __float2half_rn(a.x + b.x + c.x + d.x);
        h[q*4+1] = __float2half_rn(a.y + b.y + c.y + d.y);
        h[q*4+2] = __float2half_rn(a.z + b.z + c.z + d.z);
        h[q*4+3] = __float2half_rn(a.w + b.w + c.w + d.w);
    }
    *(uint4*)(outh + i) = *(uint4*)h;
}

// ---- merged prep: fp32->fp16 rounds (x, Wv) + W^T hi/lo splits (Wq, Wk) ----
#define NCONV 4608   // (nX + nW) / 2048
__global__ void __launch_bounds__(256)
prep_kernel(const float* __restrict__ x,  h16* __restrict__ xh,
            const float* __restrict__ Wv, h16* __restrict__ Wvh,
            const float* __restrict__ Wq, const float* __restrict__ Wk,
            h16* __restrict__ Qh, h16* __restrict__ Ql,
            h16* __restrict__ Kh, h16* __restrict__ Kl)
{
    const size_t nX = (size_t)B_ * S_ * D_;
    const size_t nW = (size_t)D_ * D_;
    const int tid = threadIdx.x;
    if (blockIdx.x < NCONV) {
        size_t i = ((size_t)blockIdx.x * 256 + tid) * 8;
        const float* in; h16* outp; size_t off;
        if (i < nX)           { in = x;  outp = xh;  off = i; }
        else if (i < nX + nW) { in = Wv; outp = Wvh; off = i - nX; }
        else return;
        float4 v0 = *(const float4*)(in + off);
        float4 v1 = *(const float4*)(in + off + 4);
        float f[8] = {v0.x, v0.y, v0.z, v0.w, v1.x, v1.y, v1.z, v1.w};
        h16 h[8];
#pragma unroll
        for (int j = 0; j < 8; j++) h[j] = __float2half_rn(f[j]);
        *(uint4*)(outp + off) = *(uint4*)h;
    } else {
        __shared__ float t[32][33];
        const int j  = blockIdx.x - NCONV;       // 0..2047
        const int zz = j >> 10;                  // 0: Wq, 1: Wk
        const int by = (j >> 5) & 31;            // e-tile
        const int bx = j & 31;                   // d-tile
        const float* W = zz ? Wk : Wq;
        h16* Th = zz ? Kh : Qh;
        h16* Tl = zz ? Kl : Ql;
        const int d0 = bx * 32, e0 = by * 32;
        const int tx = tid & 31, ty0 = tid >> 5;
#pragma unroll
        for (int q = 0; q < 4; q++) {
            int ty = ty0 + q * 8;
            t[ty][tx] = W[(size_t)(e0 + ty) * D_ + d0 + tx];
        }
        __syncthreads();
#pragma unroll
        for (int q = 0; q < 4; q++) {
            int ty = ty0 + q * 8;
            float v = t[tx][ty];                 // = W[e0+tx][d0+ty]
            h16 h = __float2half_rn(v);
            h16 l = __float2half_rn(v - __half2float(h));
            Th[(size_t)(d0 + ty) * D_ + e0 + tx] = h;
            Tl[(size_t)(d0 + ty) * D_ + e0 + tx] = l;
        }
    }
}

// ---- Rinv[i] = 1 / sum_{bx<16} Rpart[bx][i]  (i < B_*S_) ----
__global__ void __launch_bounds__(256)
rowsum16_inv(const float* __restrict__ Rp, float* __restrict__ Rinv)
{
    const int i = blockIdx.x * 256 + threadIdx.x;
    float s = 0.f;
#pragma unroll
    for (int j = 0; j < 16; j++) s += Rp[(size_t)j * (B_ * S_) + i];
    Rinv[i] = 1.f / s;
}

// ---------------------------------------------------------------------------
extern "C" void kernel_launch(void* const* d_in, const int* in_sizes, int n_in,
                              void* d_out, int out_size)
{
    const float* x  = (const float*)d_in[0];
    const float* Wq = (const float*)d_in[1];
    const float* Wk = (const float*)d_in[2];
    const float* Wv = (const float*)d_in[3];
    float* out = (float*)d_out;

    h16 *xh, *Wqth, *Wqtl, *Wkth, *Wktl, *Wvh, *Mth, *Yh, *Vth, *E;
    float *Mf, *Rpart, *Rinv;
    cudaGetSymbolAddress((void**)&xh,    g_xh);
    cudaGetSymbolAddress((void**)&Wqth,  g_Wqth); cudaGetSymbolAddress((void**)&Wqtl, g_Wqtl);
    cudaGetSymbolAddress((void**)&Wkth,  g_Wkth); cudaGetSymbolAddress((void**)&Wktl, g_Wktl);
    cudaGetSymbolAddress((void**)&Wvh,   g_Wvh);
    cudaGetSymbolAddress((void**)&Mf,    g_Mf);
    cudaGetSymbolAddress((void**)&Mth,   g_Mth);
    cudaGetSymbolAddress((void**)&Yh,    g_Yh);
    cudaGetSymbolAddress((void**)&Vth,   g_Vth);
    cudaGetSymbolAddress((void**)&E,     g_E);
    cudaGetSymbolAddress((void**)&Rpart, g_Rpart);
    cudaGetSymbolAddress((void**)&Rinv,  g_Rinv);

    cudaFuncSetAttribute(gemm_mma<1,2>, cudaFuncAttributeMaxDynamicSharedMemorySize, SM2);
    cudaFuncSetAttribute(gemm_mma<3,1>, cudaFuncAttributeMaxDynamicSharedMemorySize, SM1);
    cudaFuncSetAttribute(gemm_mma<4,1>, cudaFuncAttributeMaxDynamicSharedMemorySize, SM1);
    cudaFuncSetAttribute(yvt_kernel,    cudaFuncAttributeMaxDynamicSharedMemorySize, SM1);

    const size_t nW = (size_t)D_ * D_;
    const size_t sQKV = (size_t)S_ * D_;
    const size_t sSS  = (size_t)S_ * S_;
    const size_t sDS  = (size_t)D_ * S_;

    // merged converts + transposed weight splits
    prep_kernel<<<NCONV + 2048, 256>>>(x, xh, Wv, Wvh, Wq, Wk,
                                       Wqth, Wqtl, Wkth, Wktl);

    // Mt[d',d] = sum_e Wk[e,d'] * Wq[e,d] — split-K x4, 2-term (Wk split, Wq rounded)
    gemm_mma<1,2><<<dim3(8, 8, 4), 256, SM2>>>(
        Wkth, Wktl, Wqth, nullptr, Mf, nullptr, nullptr,
        256, D_, D_, D_, 1.f, 256, 256, nW);
    reduce4_h<<<512, 256>>>(Mf, Mth, nW);

    // fused: Y = x @ Mt^T  and  Vt[b] = Wv @ x[b]^T   (fp16, 1024 CTAs, 2/SM)
    yvt_kernel<<<1024, 256, SM1>>>(xh, Mth, Wvh, Yh, Vth);

    // E[b][q,k] = exp(sum_d Y[b][q,d] * x[b][k,d] / 32) + row partials
    gemm_mma<3,1><<<dim3(16, 16, B_), 256, SM1>>>(
        Yh, nullptr, xh, E, nullptr, nullptr, Rpart,
        D_, D_, D_, S_, 0.03125f, sQKV, sQKV, sSS);

    // Rinv[b*S+q] = 1 / sum of 16 per-tile partials
    rowsum16_inv<<<(B_ * S_) / 256, 256>>>(Rpart, Rinv);

    // out[b][d,s] = (sum_k Vt[b][d,k] * E[b][s,k]) * Rinv[b*S+s]
    gemm_mma<4,1><<<dim3(16, 8, B_), 256, SM1>>>(
        Vth, nullptr, E, nullptr, out, Rinv, nullptr,
        S_, S_, S_, S_, 1.f, sDS, sSS, sDS);
}

// round 17
// speedup vs baseline: 1.1386x; 1.0457x over previous
#include <cuda_runtime.h>
#include <cuda_fp16.h>
#include <cstdint>
#include <cstddef>

#define B_  4
#define S_  2048
#define D_  1024

typedef __half h16;

// ---------------- scratch (static __device__: allocation-free) ----------------
__device__ h16 g_xh[(size_t)B_*S_*D_];           // x rounded to fp16
__device__ h16 g_Wqth[D_*D_];                    // Wq^T [d,e] rounded
__device__ h16 g_Wkth[D_*D_];                    // Wk^T [d,e] rounded
__device__ h16 g_Wvh[D_*D_];                     // Wv rounded
__device__ float g_Mf[4 * (size_t)D_ * D_];      // split-K partials for Mt
__device__ h16 g_Mth[D_*D_];                     // Mt rounded
__device__ h16 g_Yh[(size_t)B_*S_*D_];           // Y = x @ Mt^T (rounded)
__device__ h16 g_Vth[(size_t)B_*S_*D_];          // [b][d][s] (rounded)
__device__ h16 g_E[(size_t)B_*S_*S_];            // exp(scores) fp16, unnormalized
__device__ float g_Rpart[16 * (size_t)B_*S_];    // per-(n-tile) row-sum partials

// ---------------- sm_80-era primitives (valid on plain sm_100) ----------------
__device__ __forceinline__ uint32_t smem_u32(const void* p) {
    uint32_t a;
    asm("{ .reg .u64 t; cvta.to.shared.u64 t, %1; cvt.u32.u64 %0, t; }" : "=r"(a) : "l"(p));
    return a;
}
__device__ __forceinline__ void cp16(uint32_t dst, const void* src) {
    asm volatile("cp.async.cg.shared.global [%0], [%1], 16;" :: "r"(dst), "l"(src));
}
__device__ __forceinline__ void cp_commit() {
    asm volatile("cp.async.commit_group;" ::: "memory");
}
template <int N>
__device__ __forceinline__ void cp_wait() {
    asm volatile("cp.async.wait_group %0;" :: "n"(N) : "memory");
}
__device__ __forceinline__ void ldsm_x4(uint32_t& r0, uint32_t& r1, uint32_t& r2, uint32_t& r3,
                                        uint32_t addr) {
    asm volatile("ldmatrix.sync.aligned.m8n8.x4.shared.b16 {%0,%1,%2,%3}, [%4];"
                 : "=r"(r0), "=r"(r1), "=r"(r2), "=r"(r3) : "r"(addr));
}
__device__ __forceinline__ void mma16816(float* c, const uint32_t* a, uint32_t b0, uint32_t b1) {
    asm volatile(
        "mma.sync.aligned.m16n8k16.row.col.f32.f16.f16.f32 "
        "{%0,%1,%2,%3}, {%4,%5,%6,%7}, {%8,%9}, {%0,%1,%2,%3};"
        : "+f"(c[0]), "+f"(c[1]), "+f"(c[2]), "+f"(c[3])
        : "r"(a[0]), "r"(a[1]), "r"(a[2]), "r"(a[3]), "r"(b0), "r"(b1));
}

// ---------------------------------------------------------------------------
// HMMA GEMM tile body (R14 config): C[128,128] at (m0,n0) = f(A@B^T) over K.
// Plain fp16 1-term; 4-stage cp.async, prefetch dist 2, SINGLE sync per chunk.
//   hazard proof: issue at iter kc writes stage (kc+2)&3, last read at iter
//   kc-2; every warp reaching the issue passed sync(kc-1), which all warps
//   reach only after finishing compute(kc-2).
// EPI 1: Cf = alpha*acc   EPI 2: Chi = fp16(acc)
// EPI 3: Chi = fp16(expf(alpha*acc)) + per-row partial sums -> Rp[row]
// EPI 4: Cf = acc * (1/sum16(RpIn col partials))  (softmax normalization)
// 256 threads, rows padded to 80 B (conflict-free ldmatrix).
// ---------------------------------------------------------------------------
#define ROWB      80
#define TILEB     (128 * ROWB)          // 10240 B per operand tile
#define SM1       (4 * 2 * TILEB)       //  81920 (4 stages x 2 tiles, 2 CTA/SM)

template <int EPI>
__device__ __forceinline__ void
gemm_body(const h16* __restrict__ Ah, const h16* __restrict__ Bh,
          h16* __restrict__ Chi, float* __restrict__ Cf,
          const float* __restrict__ RpIn, float* __restrict__ Rp,
          int K, int ldA, int ldB, int ldC, float alpha,
          int m0, int n0, char* smem)
{
    constexpr int STB = 2 * TILEB;

    const uint32_t sbase = smem_u32(smem);
    const int tid  = threadIdx.x;
    const int warp = tid >> 5;
    const int lane = tid & 31;

    const int wm = (warp >> 2) * 64;    // warp tile: 64 (m) x 32 (n)
    const int wn = (warp & 3) * 32;
    const int nch = K >> 5;             // K-chunks of 32 (>= 8 for all calls)

    float acc[4][4][4];
#pragma unroll
    for (int mi = 0; mi < 4; mi++)
#pragma unroll
        for (int ni = 0; ni < 4; ni++)
#pragma unroll
            for (int r = 0; r < 4; r++) acc[mi][ni][r] = 0.f;

    const int row0 = tid >> 2;          // 0..63 ; second row = +64
    const int seg  = tid & 3;           // 16B segment within 64B of row data

    auto issue = [&](int kc, int st) {
        const int kk = kc << 5;
        const uint32_t s0 = sbase + st * STB;
#pragma unroll
        for (int p = 0; p < 2; p++) {
            const int row = row0 + p * 64;
            cp16(s0 + row * ROWB + seg * 16,
                 (const char*)(Ah + (size_t)(m0 + row) * ldA + kk) + seg * 16);
            cp16(s0 + TILEB + row * ROWB + seg * 16,
                 (const char*)(Bh + (size_t)(n0 + row) * ldB + kk) + seg * 16);
        }
        cp_commit();
    };

    issue(0, 0);
    issue(1, 1);

    for (int kc = 0; kc < nch; kc++) {
        const int st = kc & 3;
        if (kc + 2 < nch) issue(kc + 2, (kc + 2) & 3);
        else              cp_commit();           // empty group keeps count uniform
        cp_wait<2>();                            // group kc complete
        __syncthreads();

        const uint32_t s0 = sbase + st * STB;
        const uint32_t lrow = (lane & 15) * ROWB + (lane >> 4) * 16;

#pragma unroll
        for (int ks = 0; ks < 2; ks++) {
            uint32_t ah[4][4], bh[2][4];
#pragma unroll
            for (int mi = 0; mi < 4; mi++)
                ldsm_x4(ah[mi][0], ah[mi][1], ah[mi][2], ah[mi][3],
                        s0 + (wm + mi * 16) * ROWB + lrow + ks * 32);
#pragma unroll
            for (int nb = 0; nb < 2; nb++)
                ldsm_x4(bh[nb][0], bh[nb][1], bh[nb][2], bh[nb][3],
                        s0 + TILEB + (wn + nb * 16) * ROWB + lrow + ks * 32);
#pragma unroll
            for (int mi = 0; mi < 4; mi++)
#pragma unroll
                for (int ni = 0; ni < 4; ni++) {
                    const int g = ni >> 1, h = ni & 1;
                    mma16816(acc[mi][ni], ah[mi], bh[g][h], bh[g][h + 2]);
                }
        }
    }

    // ---- EPI 4 prologue: per-column 1/rowsum from 16 partials into smem.
    // Scratch = stage 0 bytes [0,512); laggards on the final chunk read stage
    // (nch-1)&3 = 3 for K=2048 — disjoint, no hazard. Sync orders write->read.
    float* sp = (float*)smem;
    if (EPI == 4) {
        if (tid < 128) {
            float s = 0.f;
#pragma unroll
            for (int j = 0; j < 16; j++) s += RpIn[(size_t)j * (B_ * S_) + tid];
            sp[tid] = 1.f / s;
        }
        __syncthreads();
    }

    // ---- epilogue: d0,d1 = row g, cols 2t,2t+1 ; d2,d3 = row g+8
    const int rr = lane >> 2;
    const int cc = (lane & 3) * 2;
    float rp[4][2];
    if (EPI == 3) {
#pragma unroll
        for (int mi = 0; mi < 4; mi++) { rp[mi][0] = 0.f; rp[mi][1] = 0.f; }
    }
#pragma unroll
    for (int mi = 0; mi < 4; mi++) {
#pragma unroll
        for (int ni = 0; ni < 4; ni++) {
            const int r = m0 + wm + mi * 16 + rr;
            const int c = n0 + wn + ni * 8 + cc;
            const float* a = acc[mi][ni];
            float rs0 = 0.f, rs1 = 0.f;
            if (EPI == 4) {
                const int lc = wn + ni * 8 + cc;
                rs0 = sp[lc]; rs1 = sp[lc + 1];
            }
#pragma unroll
            for (int h = 0; h < 2; h++) {
                const size_t o = (size_t)(r + h * 8) * ldC + c;
                if (EPI == 2) {
                    *(__half2*)(Chi + o) =
                        __halves2half2(__float2half_rn(a[2*h]), __float2half_rn(a[2*h + 1]));
                } else if (EPI == 3) {
                    float e0 = __expf(alpha * a[2*h]);
                    float e1 = __expf(alpha * a[2*h + 1]);
                    *(__half2*)(Chi + o) =
                        __halves2half2(__float2half_rn(e0), __float2half_rn(e1));
                    rp[mi][h] += e0 + e1;
                } else if (EPI == 4) {
                    float2 v; v.x = a[2*h] * rs0; v.y = a[2*h + 1] * rs1;
                    *(float2*)(Cf + o) = v;
                } else {
                    float2 v; v.x = alpha * a[2*h]; v.y = alpha * a[2*h + 1];
                    *(float2*)(Cf + o) = v;
                }
            }
        }
    }
    if (EPI == 3) {
        // quad-reduce across the 4 lanes sharing each row, then 4-warp combine.
        // Scratch = stage 0 bytes [0,2KB); laggards on the final chunk read
        // stage (nch-1)&3 = 3 for K=1024 — disjoint, no hazard.
#pragma unroll
        for (int mi = 0; mi < 4; mi++)
#pragma unroll
            for (int h = 0; h < 2; h++) {
                float s = rp[mi][h];
                s += __shfl_xor_sync(0xFFFFFFFFu, s, 1);
                s += __shfl_xor_sync(0xFFFFFFFFu, s, 2);
                if ((lane & 3) == 0)
                    sp[(wm + mi * 16 + rr + h * 8) * 4 + (warp & 3)] = s;
            }
        __syncthreads();
        if (tid < 128)
            Rp[tid] = sp[tid * 4] + sp[tid * 4 + 1] + sp[tid * 4 + 2] + sp[tid * 4 + 3];
    }
}

// ---- generic wrapper kernel (tiles on blockIdx.x/y, batch/split on z) ----
template <int EPI>
__global__ void __launch_bounds__(256, 2)
gemm_mma(const h16* __restrict__ Ah, const h16* __restrict__ Bh,
         h16* __restrict__ Chi, float* __restrict__ Cf,
         const float* __restrict__ RpIn, float* __restrict__ Rp,
         int K, int ldA, int ldB, int ldC, float alpha,
         size_t aStr, size_t bStr, size_t cStr)
{
    extern __shared__ char smem[];
    const size_t z = blockIdx.z;
    float* Rp_loc = (EPI == 3)
        ? Rp + (size_t)blockIdx.x * (B_ * S_) + z * S_ + blockIdx.y * 128 : nullptr;
    const float* RpIn_loc = (EPI == 4)
        ? RpIn + z * S_ + blockIdx.x * 128 : nullptr;
    gemm_body<EPI>(Ah + z * aStr, Bh + z * bStr,
                   (EPI == 2 || EPI == 3) ? Chi + z * cStr : nullptr,
                   (EPI == 1 || EPI == 4) ? Cf + z * cStr : nullptr,
                   RpIn_loc, Rp_loc,
                   K, ldA, ldB, ldC, alpha,
                   blockIdx.y * 128, blockIdx.x * 128, smem);
}

// ---- fused Y + Vt kernel: 1024 linear CTAs, both 1-term fp16 K=1024 ----
__global__ void __launch_bounds__(256, 2)
yvt_kernel(const h16* __restrict__ xh, const h16* __restrict__ Mth,
           const h16* __restrict__ Wvh, h16* __restrict__ Yh, h16* __restrict__ Vth)
{
    extern __shared__ char smem[];
    const int idx = blockIdx.x;
    if (idx < 512) {
        // Y[s,d'] = sum_d x[s,d] * Mt[d',d]   M=8192, N=1024
        const int by = idx >> 3, bx = idx & 7;
        gemm_body<2>(xh, Mth, Yh, nullptr, nullptr, nullptr,
                     D_, D_, D_, D_, 1.f, by * 128, bx * 128, smem);
    } else {
        // Vt[b][d,s] = sum_e Wv[d,e] * x[b][s,e]   per batch: M=1024, N=2048
        const int j = idx - 512;
        const int bx = j & 15, by = (j >> 4) & 7, z = j >> 7;
        gemm_body<2>(Wvh, xh + (size_t)z * S_ * D_,
                     Vth + (size_t)z * D_ * S_, nullptr, nullptr, nullptr,
                     D_, D_, D_, S_, 1.f, by * 128, bx * 128, smem);
    }
}

// ---- reduce 4 split-K fp32 partials -> fp16 (8 elems/thread for MLP) ----
__global__ void __launch_bounds__(256)
reduce4_h(const float* __restrict__ P, h16* __restrict__ outh, size_t n)
{
    size_t i = ((size_t)blockIdx.x * 256 + threadIdx.x) * 8;
    if (i >= n) return;
    h16 h[8];
#pragma unroll
    for (int q = 0; q < 2; q++) {
        size_t j = i + q * 4;
        float4 a = *(const float4*)(P + j);
        float4 b = *(const float4*)(P + n + j);
        float4 c = *(const float4*)(P + 2 * n + j);
        float4 d = *(const float4*)(P + 3 * n + j);
        h[q*4+0] = __float2half_rn(a.x + b.x + c.x + d.x);
        h[q*4+1] = __float2half_rn(a.y + b.y + c.y + d.y);
        h[q*4+2] = __float2half_rn(a.z + b.z + c.z + d.z);
        h[q*4+3] = __float2half_rn(a.w + b.w + c.w + d.w);
    }
    *(uint4*)(outh + i) = *(uint4*)h;
}

// ---- merged prep: fp32->fp16 rounds (x, Wv) + W^T rounds (Wq, Wk) ----
#define NCONV 4608   // (nX + nW) / 2048
__global__ void __launch_bounds__(256)
prep_kernel(const float* __restrict__ x,  h16* __restrict__ xh,
            const float* __restrict__ Wv, h16* __restrict__ Wvh,
            const float* __restrict__ Wq, const float* __restrict__ Wk,
            h16* __restrict__ Qt, h16* __restrict__ Kt)
{
    const size_t nX = (size_t)B_ * S_ * D_;
    const size_t nW = (size_t)D_ * D_;
    const int tid = threadIdx.x;
    if (blockIdx.x < NCONV) {
        size_t i = ((size_t)blockIdx.x * 256 + tid) * 8;
        const float* in; h16* outp; size_t off;
        if (i < nX)           { in = x;  outp = xh;  off = i; }
        else if (i < nX + nW) { in = Wv; outp = Wvh; off = i - nX; }
        else return;
        float4 v0 = *(const float4*)(in + off);
        float4 v1 = *(const float4*)(in + off + 4);
        float f[8] = {v0.x, v0.y, v0.z, v0.w, v1.x, v1.y, v1.z, v1.w};
        h16 h[8];
#pragma unroll
        for (int j = 0; j < 8; j++) h[j] = __float2half_rn(f[j]);
        *(uint4*)(outp + off) = *(uint4*)h;
    } else {
        __shared__ float t[32][33];
        const int j  = blockIdx.x - NCONV;       // 0..2047
        const int zz = j >> 10;                  // 0: Wq, 1: Wk
        const int by = (j >> 5) & 31;            // e-tile
        const int bx = j & 31;                   // d-tile
        const float* W = zz ? Wk : Wq;
        h16* Th = zz ? Kt : Qt;
        const int d0 = bx * 32, e0 = by * 32;
        const int tx = tid & 31, ty0 = tid >> 5;
#pragma unroll
        for (int q = 0; q < 4; q++) {
            int ty = ty0 + q * 8;
            t[ty][tx] = W[(size_t)(e0 + ty) * D_ + d0 + tx];
        }
        __syncthreads();
#pragma unroll
        for (int q = 0; q < 4; q++) {
            int ty = ty0 + q * 8;
            Th[(size_t)(d0 + ty) * D_ + e0 + tx] = __float2half_rn(t[tx][ty]);
        }
    }
}

// ---------------------------------------------------------------------------
extern "C" void kernel_launch(void* const* d_in, const int* in_sizes, int n_in,
                              void* d_out, int out_size)
{
    const float* x  = (const float*)d_in[0];
    const float* Wq = (const float*)d_in[1];
    const float* Wk = (const float*)d_in[2];
    const float* Wv = (const float*)d_in[3];
    float* out = (float*)d_out;

    h16 *xh, *Wqth, *Wkth, *Wvh, *Mth, *Yh, *Vth, *E;
    float *Mf, *Rpart;
    cudaGetSymbolAddress((void**)&xh,    g_xh);
    cudaGetSymbolAddress((void**)&Wqth,  g_Wqth);
    cudaGetSymbolAddress((void**)&Wkth,  g_Wkth);
    cudaGetSymbolAddress((void**)&Wvh,   g_Wvh);
    cudaGetSymbolAddress((void**)&Mf,    g_Mf);
    cudaGetSymbolAddress((void**)&Mth,   g_Mth);
    cudaGetSymbolAddress((void**)&Yh,    g_Yh);
    cudaGetSymbolAddress((void**)&Vth,   g_Vth);
    cudaGetSymbolAddress((void**)&E,     g_E);
    cudaGetSymbolAddress((void**)&Rpart, g_Rpart);

    cudaFuncSetAttribute(gemm_mma<1>, cudaFuncAttributeMaxDynamicSharedMemorySize, SM1);
    cudaFuncSetAttribute(gemm_mma<3>, cudaFuncAttributeMaxDynamicSharedMemorySize, SM1);
    cudaFuncSetAttribute(gemm_mma<4>, cudaFuncAttributeMaxDynamicSharedMemorySize, SM1);
    cudaFuncSetAttribute(yvt_kernel,  cudaFuncAttributeMaxDynamicSharedMemorySize, SM1);

    const size_t nW = (size_t)D_ * D_;
    const size_t sQKV = (size_t)S_ * D_;
    const size_t sSS  = (size_t)S_ * S_;
    const size_t sDS  = (size_t)D_ * S_;

    // merged converts + transposed weight rounds
    prep_kernel<<<NCONV + 2048, 256>>>(x, xh, Wv, Wvh, Wq, Wk, Wqth, Wkth);

    // Mt[d',d] = sum_e Wk[e,d'] * Wq[e,d] — split-K x4, plain fp16
    gemm_mma<1><<<dim3(8, 8, 4), 256, SM1>>>(
        Wkth, Wqth, nullptr, Mf, nullptr, nullptr,
        256, D_, D_, D_, 1.f, 256, 256, nW);
    reduce4_h<<<512, 256>>>(Mf, Mth, nW);

    // fused: Y = x @ Mt^T  and  Vt[b] = Wv @ x[b]^T   (fp16, 1024 CTAs, 2/SM)
    yvt_kernel<<<1024, 256, SM1>>>(xh, Mth, Wvh, Yh, Vth);

    // E[b][q,k] = exp(sum_d Y[b][q,d] * x[b][k,d] / 32) + row partials
    gemm_mma<3><<<dim3(16, 16, B_), 256, SM1>>>(
        Yh, xh, E, nullptr, nullptr, Rpart,
        D_, D_, D_, S_, 0.03125f, sQKV, sQKV, sSS);

    // out[b][d,s] = (sum_k Vt[b][d,k] * E[b][s,k]) / rowsum  (Rinv in-kernel)
    gemm_mma<4><<<dim3(16, 8, B_), 256, SM1>>>(
        Vth, E, nullptr, out, Rpart, nullptr,
        S_, S_, S_, S_, 1.f, sDS, sSS, sDS);
}